// round 2
// baseline (speedup 1.0000x reference)
#include <cuda_runtime.h>
#include <cstdint>
#include <cstddef>

#define B_ 512
#define K_ 128
#define D_ 512

// Scratch (static device globals — no allocation in kernel_launch).
__device__ float  g_cost[(size_t)B_ * K_ * K_];   // 32 MB
__device__ int    g_perm[B_ * K_];                // row -> matched column
__device__ double g_part[B_];                     // per-batch loss partial

// ---------------------------------------------------------------------------
// Kernel 1: per-batch cost matrix  C = ||x||^2 + ||y||^2 - 2 X Y^T
// One block per batch, 256 threads, 8x8 register tile per thread.
// ---------------------------------------------------------------------------
__global__ void __launch_bounds__(256) cost_kernel(const float* __restrict__ X,
                                                   const float* __restrict__ Y)
{
    int b = blockIdx.x;
    const float* x = X + (size_t)b * K_ * D_;
    const float* y = Y + (size_t)b * K_ * D_;
    float* cb = g_cost + (size_t)b * K_ * K_;

    __shared__ float xs[32][132];   // [k][i], padded
    __shared__ float ys[32][132];   // [k][j], padded
    __shared__ float sn[2][128];    // row norms of x (0) and y (1)

    int tid = threadIdx.x;

    // Row squared norms: threads 0..127 -> x rows, 128..255 -> y rows.
    {
        const float* src = (tid < 128) ? x : y;
        int r = tid & 127;
        const float4* p4 = reinterpret_cast<const float4*>(src + (size_t)r * D_);
        float s = 0.f;
        #pragma unroll 8
        for (int k = 0; k < D_ / 4; ++k) {
            float4 v = p4[k];
            s += v.x * v.x + v.y * v.y + v.z * v.z + v.w * v.w;
        }
        sn[tid >> 7][r] = s;
    }

    float acc[8][8];
    #pragma unroll
    for (int a = 0; a < 8; ++a)
        #pragma unroll
        for (int c = 0; c < 8; ++c) acc[a][c] = 0.f;

    int ti = tid >> 4;      // 0..15 -> rows ti*8..ti*8+7
    int tj = tid & 15;      // 0..15 -> cols tj*8..tj*8+7

    for (int k0 = 0; k0 < D_; k0 += 32) {
        __syncthreads();
        // Load 128x32 tiles of X and Y, transposed into [k][row].
        #pragma unroll
        for (int l = 0; l < 4; ++l) {
            int f = tid + l * 256;          // 0..1023
            int row = f >> 3;               // 0..127
            int c = f & 7;                  // float4 index along k
            float4 vx = *reinterpret_cast<const float4*>(x + (size_t)row * D_ + k0 + c * 4);
            float4 vy = *reinterpret_cast<const float4*>(y + (size_t)row * D_ + k0 + c * 4);
            int kk = c * 4;
            xs[kk + 0][row] = vx.x; xs[kk + 1][row] = vx.y;
            xs[kk + 2][row] = vx.z; xs[kk + 3][row] = vx.w;
            ys[kk + 0][row] = vy.x; ys[kk + 1][row] = vy.y;
            ys[kk + 2][row] = vy.z; ys[kk + 3][row] = vy.w;
        }
        __syncthreads();
        #pragma unroll 4
        for (int k = 0; k < 32; ++k) {
            float4 t0 = *reinterpret_cast<const float4*>(&xs[k][ti * 8]);
            float4 t1 = *reinterpret_cast<const float4*>(&xs[k][ti * 8 + 4]);
            float4 t2 = *reinterpret_cast<const float4*>(&ys[k][tj * 8]);
            float4 t3 = *reinterpret_cast<const float4*>(&ys[k][tj * 8 + 4]);
            float a[8]  = {t0.x, t0.y, t0.z, t0.w, t1.x, t1.y, t1.z, t1.w};
            float bb[8] = {t2.x, t2.y, t2.z, t2.w, t3.x, t3.y, t3.z, t3.w};
            #pragma unroll
            for (int ii = 0; ii < 8; ++ii)
                #pragma unroll
                for (int jj = 0; jj < 8; ++jj)
                    acc[ii][jj] = fmaf(a[ii], bb[jj], acc[ii][jj]);
        }
    }

    // Write out: c[i][j] = sn_x[i] + sn_y[j] - 2*dot
    #pragma unroll
    for (int ii = 0; ii < 8; ++ii) {
        int i = ti * 8 + ii;
        float sxi = sn[0][i];
        int jb = tj * 8;
        float4 o0, o1;
        o0.x = sxi + sn[1][jb + 0] - 2.f * acc[ii][0];
        o0.y = sxi + sn[1][jb + 1] - 2.f * acc[ii][1];
        o0.z = sxi + sn[1][jb + 2] - 2.f * acc[ii][2];
        o0.w = sxi + sn[1][jb + 3] - 2.f * acc[ii][3];
        o1.x = sxi + sn[1][jb + 4] - 2.f * acc[ii][4];
        o1.y = sxi + sn[1][jb + 5] - 2.f * acc[ii][5];
        o1.z = sxi + sn[1][jb + 6] - 2.f * acc[ii][6];
        o1.w = sxi + sn[1][jb + 7] - 2.f * acc[ii][7];
        *reinterpret_cast<float4*>(&cb[(size_t)i * K_ + jb])     = o0;
        *reinterpret_cast<float4*>(&cb[(size_t)i * K_ + jb + 4]) = o1;
    }
}

// ---------------------------------------------------------------------------
// Kernel 2: Jonker-Volgenant LAP, ONE WARP per batch, 4 columns per lane.
// All reductions are warp-level (REDUX / ballot / shfl) — no block barriers.
// ---------------------------------------------------------------------------
__device__ __forceinline__ unsigned int fenc(float f)
{
    unsigned int u = __float_as_uint(f);
    return (u & 0x80000000u) ? ~u : (u | 0x80000000u);
}
__device__ __forceinline__ float fdec(unsigned int u)
{
    unsigned int bits = (u & 0x80000000u) ? (u ^ 0x80000000u) : ~u;
    return __uint_as_float(bits);
}

__global__ void __launch_bounds__(32) hungarian_kernel()
{
    extern __shared__ float cost_s[];       // K_*K_ floats (64 KB)
    __shared__ float u_s[K_ + 1];
    __shared__ int   p_s[K_ + 1];           // p[j] = row matched to column j
    __shared__ int   way_s[K_ + 1];

    int b = blockIdx.x;
    int L = threadIdx.x;                    // lane; owns columns 1+L+32c, c=0..3

    // Stage cost matrix into shared memory (vectorized, coalesced).
    {
        const float4* src = reinterpret_cast<const float4*>(g_cost + (size_t)b * K_ * K_);
        float4* dst = reinterpret_cast<float4*>(cost_s);
        #pragma unroll
        for (int q = 0; q < (K_ * K_ / 4) / 32; ++q)
            dst[L + q * 32] = src[L + q * 32];
    }
    #pragma unroll
    for (int c = 0; c < 4; ++c) {
        u_s[1 + L + 32 * c] = 0.f;
        p_s[1 + L + 32 * c] = 0;
    }
    if (L == 0) { u_s[0] = 0.f; p_s[0] = 0; }
    float v[4] = {0.f, 0.f, 0.f, 0.f};
    __syncwarp();

    for (int i = 1; i <= K_; ++i) {
        if (L == 0) p_s[0] = i;
        float minv[4] = {3.0e38f, 3.0e38f, 3.0e38f, 3.0e38f};
        unsigned int used = 0;              // bit c: column 1+L+32c used
        int pcol[4];                        // cached p[col] (stable within phase)
        #pragma unroll
        for (int c = 0; c < 4; ++c) pcol[c] = p_s[1 + L + 32 * c];
        __syncwarp();

        int j0 = 0;
        int i0 = i;                         // p_s[0] == i
        while (true) {
            // mark used[j0]
            if (j0 > 0) {
                int idx = j0 - 1;
                if ((idx & 31) == L) used |= 1u << (idx >> 5);
            }
            float ui0 = u_s[i0];
            const float* crow = cost_s + (size_t)(i0 - 1) * K_;
            unsigned int key = 0xFFFFFFFFu;
            int bc = 0;
            #pragma unroll
            for (int c = 0; c < 4; ++c) {
                float cur = crow[L + 32 * c] - ui0 - v[c];
                bool fr = !((used >> c) & 1u);
                if (fr && cur < minv[c]) { minv[c] = cur; way_s[1 + L + 32 * c] = j0; }
                unsigned int kc = fr ? fenc(minv[c]) : 0xFFFFFFFFu;
                if (kc < key) { key = kc; bc = c; }
            }
            unsigned int m   = __reduce_min_sync(0xFFFFFFFFu, key);
            unsigned int bal = __ballot_sync(0xFFFFFFFFu, key == m);
            int srcl = __ffs(bal) - 1;
            int j1  = __shfl_sync(0xFFFFFFFFu, 1 + L + 32 * bc, srcl);
            int pj1 = __shfl_sync(0xFFFFFFFFu, pcol[bc], srcl);   // p[j1]
            float delta = fdec(m);
            // dual updates: used columns' rows (all distinct) + virtual col 0
            #pragma unroll
            for (int c = 0; c < 4; ++c) {
                if ((used >> c) & 1u) {
                    u_s[pcol[c]] += delta;
                    v[c] -= delta;
                } else {
                    minv[c] -= delta;
                }
            }
            if (L == 0) u_s[i] += delta;    // p_s[0] == i
            __syncwarp();
            j0 = j1;
            i0 = pj1;
            if (pj1 == 0) break;
        }
        // Augment along alternating path (serial pointer chase, lane 0).
        if (L == 0) {
            int jj = j0;
            while (jj != 0) { int jp = way_s[jj]; p_s[jj] = p_s[jp]; jj = jp; }
        }
        __syncwarp();
    }
    // col_ind[p[j]-1] = j-1
    #pragma unroll
    for (int c = 0; c < 4; ++c) {
        int col = 1 + L + 32 * c;
        g_perm[b * K_ + (p_s[col] - 1)] = col - 1;
    }
}

// ---------------------------------------------------------------------------
// Kernel 3: exact MSE partials per batch (fp32 diffs like reference, fp64 sum)
// ---------------------------------------------------------------------------
__global__ void __launch_bounds__(256) loss_kernel(const float* __restrict__ X,
                                                   const float* __restrict__ Y)
{
    int b = blockIdx.x;
    int tid = threadIdx.x, lane = tid & 31, w = tid >> 5;
    const float* x = X + (size_t)b * K_ * D_;
    const float* y = Y + (size_t)b * K_ * D_;

    float s = 0.f;
    for (int i = w; i < K_; i += 8) {
        int c = g_perm[b * K_ + i];
        const float4* xp = reinterpret_cast<const float4*>(x + (size_t)i * D_);
        const float4* yp = reinterpret_cast<const float4*>(y + (size_t)c * D_);
        #pragma unroll
        for (int q = 0; q < 4; ++q) {
            float4 a  = xp[lane + q * 32];
            float4 bb = yp[lane + q * 32];
            float dx = a.x - bb.x, dy = a.y - bb.y;
            float dz = a.z - bb.z, dw = a.w - bb.w;
            s += dx * dx + dy * dy + dz * dz + dw * dw;
        }
    }
    double ds = (double)s;
    #pragma unroll
    for (int off = 16; off; off >>= 1)
        ds += __shfl_down_sync(0xFFFFFFFFu, ds, off);
    __shared__ double wsum[8];
    if (lane == 0) wsum[w] = ds;
    __syncthreads();
    if (tid == 0) {
        double tot = 0.0;
        #pragma unroll
        for (int q = 0; q < 8; ++q) tot += wsum[q];
        g_part[b] = tot;
    }
}

__global__ void __launch_bounds__(512) final_kernel(float* __restrict__ out)
{
    __shared__ double s[512];
    int t = threadIdx.x;
    s[t] = g_part[t];
    __syncthreads();
    for (int stride = 256; stride; stride >>= 1) {
        if (t < stride) s[t] += s[t + stride];
        __syncthreads();
    }
    if (t == 0) out[0] = (float)(s[0] / ((double)B_ * K_ * D_));
}

// ---------------------------------------------------------------------------
extern "C" void kernel_launch(void* const* d_in, const int* in_sizes, int n_in,
                              void* d_out, int out_size)
{
    (void)in_sizes; (void)n_in; (void)out_size;
    const float* X = (const float*)d_in[0];
    const float* Y = (const float*)d_in[1];
    float* out = (float*)d_out;

    cudaFuncSetAttribute(hungarian_kernel,
                         cudaFuncAttributeMaxDynamicSharedMemorySize,
                         K_ * K_ * (int)sizeof(float));

    cost_kernel<<<B_, 256>>>(X, Y);
    hungarian_kernel<<<B_, 32, K_ * K_ * sizeof(float)>>>();
    loss_kernel<<<B_, 256>>>(X, Y);
    final_kernel<<<1, 512>>>(out);
}

// round 3
// speedup vs baseline: 2.9183x; 2.9183x over previous
#include <cuda_runtime.h>
#include <cstdint>
#include <cstddef>

#define B_ 512
#define K_ 128
#define D_ 512

// Scratch (static device globals — no allocation in kernel_launch).
__device__ float  g_cost[(size_t)B_ * K_ * K_];   // 32 MB
__device__ int    g_perm[B_ * K_];                // row -> matched column
__device__ double g_accum;                         // zero-init; self-resetting
__device__ unsigned int g_count;                   // zero-init; self-resetting

// ---------------------------------------------------------------------------
// Kernel 1: per-batch cost matrix  C = ||x||^2 + ||y||^2 - 2 X Y^T
// One block per batch, 256 threads, 8x8 register tile per thread.
// ---------------------------------------------------------------------------
__global__ void __launch_bounds__(256) cost_kernel(const float* __restrict__ X,
                                                   const float* __restrict__ Y)
{
    int b = blockIdx.x;
    const float* x = X + (size_t)b * K_ * D_;
    const float* y = Y + (size_t)b * K_ * D_;
    float* cb = g_cost + (size_t)b * K_ * K_;

    __shared__ float xs[32][132];   // [k][i], padded
    __shared__ float ys[32][132];   // [k][j], padded
    __shared__ float sn[2][128];    // row norms of x (0) and y (1)

    int tid = threadIdx.x;

    // Row squared norms: threads 0..127 -> x rows, 128..255 -> y rows.
    {
        const float* src = (tid < 128) ? x : y;
        int r = tid & 127;
        const float4* p4 = reinterpret_cast<const float4*>(src + (size_t)r * D_);
        float s = 0.f;
        #pragma unroll 8
        for (int k = 0; k < D_ / 4; ++k) {
            float4 v = p4[k];
            s += v.x * v.x + v.y * v.y + v.z * v.z + v.w * v.w;
        }
        sn[tid >> 7][r] = s;
    }

    float acc[8][8];
    #pragma unroll
    for (int a = 0; a < 8; ++a)
        #pragma unroll
        for (int c = 0; c < 8; ++c) acc[a][c] = 0.f;

    int ti = tid >> 4;      // 0..15 -> rows ti*8..ti*8+7
    int tj = tid & 15;      // 0..15 -> cols tj*8..tj*8+7

    for (int k0 = 0; k0 < D_; k0 += 32) {
        __syncthreads();
        // Load 128x32 tiles of X and Y, transposed into [k][row].
        #pragma unroll
        for (int l = 0; l < 4; ++l) {
            int f = tid + l * 256;          // 0..1023
            int row = f >> 3;               // 0..127
            int c = f & 7;                  // float4 index along k
            float4 vx = *reinterpret_cast<const float4*>(x + (size_t)row * D_ + k0 + c * 4);
            float4 vy = *reinterpret_cast<const float4*>(y + (size_t)row * D_ + k0 + c * 4);
            int kk = c * 4;
            xs[kk + 0][row] = vx.x; xs[kk + 1][row] = vx.y;
            xs[kk + 2][row] = vx.z; xs[kk + 3][row] = vx.w;
            ys[kk + 0][row] = vy.x; ys[kk + 1][row] = vy.y;
            ys[kk + 2][row] = vy.z; ys[kk + 3][row] = vy.w;
        }
        __syncthreads();
        #pragma unroll 4
        for (int k = 0; k < 32; ++k) {
            float4 t0 = *reinterpret_cast<const float4*>(&xs[k][ti * 8]);
            float4 t1 = *reinterpret_cast<const float4*>(&xs[k][ti * 8 + 4]);
            float4 t2 = *reinterpret_cast<const float4*>(&ys[k][tj * 8]);
            float4 t3 = *reinterpret_cast<const float4*>(&ys[k][tj * 8 + 4]);
            float a[8]  = {t0.x, t0.y, t0.z, t0.w, t1.x, t1.y, t1.z, t1.w};
            float bb[8] = {t2.x, t2.y, t2.z, t2.w, t3.x, t3.y, t3.z, t3.w};
            #pragma unroll
            for (int ii = 0; ii < 8; ++ii)
                #pragma unroll
                for (int jj = 0; jj < 8; ++jj)
                    acc[ii][jj] = fmaf(a[ii], bb[jj], acc[ii][jj]);
        }
    }

    // Write out: c[i][j] = sn_x[i] + sn_y[j] - 2*dot
    #pragma unroll
    for (int ii = 0; ii < 8; ++ii) {
        int i = ti * 8 + ii;
        float sxi = sn[0][i];
        int jb = tj * 8;
        float4 o0, o1;
        o0.x = sxi + sn[1][jb + 0] - 2.f * acc[ii][0];
        o0.y = sxi + sn[1][jb + 1] - 2.f * acc[ii][1];
        o0.z = sxi + sn[1][jb + 2] - 2.f * acc[ii][2];
        o0.w = sxi + sn[1][jb + 3] - 2.f * acc[ii][3];
        o1.x = sxi + sn[1][jb + 4] - 2.f * acc[ii][4];
        o1.y = sxi + sn[1][jb + 5] - 2.f * acc[ii][5];
        o1.z = sxi + sn[1][jb + 6] - 2.f * acc[ii][6];
        o1.w = sxi + sn[1][jb + 7] - 2.f * acc[ii][7];
        *reinterpret_cast<float4*>(&cb[(size_t)i * K_ + jb])     = o0;
        *reinterpret_cast<float4*>(&cb[(size_t)i * K_ + jb + 4]) = o1;
    }
}

// ---------------------------------------------------------------------------
// Kernel 2: Jonker-Volgenant LAP, ONE WARP per batch.
// Lane L owns columns 4L..4L+3 (0-based). All per-step state in registers;
// p[] and way[] packed 4x8-bit per lane; inner loop has NO smem traffic
// except one LDS.128 (the cost row) and NO __syncwarp.
// Init: column reduction (computed during the gmem->smem copy) + greedy
// row claim — typically matches ~2/3 of rows before any Dijkstra phase.
// ---------------------------------------------------------------------------
__device__ __forceinline__ unsigned int fenc(float f)
{
    unsigned int u = __float_as_uint(f);
    return (u & 0x80000000u) ? ~u : (u | 0x80000000u);
}
__device__ __forceinline__ float fdec(unsigned int u)
{
    unsigned int bits = (u & 0x80000000u) ? (u ^ 0x80000000u) : ~u;
    return __uint_as_float(bits);
}

__global__ void __launch_bounds__(32) hungarian_kernel()
{
    extern __shared__ float cost_s[];       // K_*K_ floats (64 KB)
    __shared__ float u_s[K_ + 1];           // row duals (row ids 1..K_)
    __shared__ int   rowclaim[K_];          // >=0: row matched

    const unsigned FULL = 0xFFFFFFFFu;
    int b = blockIdx.x;
    int L = threadIdx.x;

    // ---- Stage cost matrix; fold column-reduction into the copy. ----
    // float4 index e = L + 32q covers floats 4L+128q.. -> row q, cols 4L..4L+3:
    // every float4 this lane copies belongs to exactly its own 4 columns.
    float cm0 = 3.0e38f, cm1 = 3.0e38f, cm2 = 3.0e38f, cm3 = 3.0e38f;
    int   am0 = 0, am1 = 0, am2 = 0, am3 = 0;
    {
        const float4* src = reinterpret_cast<const float4*>(g_cost + (size_t)b * K_ * K_);
        float4* dst = reinterpret_cast<float4*>(cost_s);
        #pragma unroll 8
        for (int q = 0; q < K_; ++q) {
            float4 vv = src[L + 32 * q];
            dst[L + 32 * q] = vv;
            if (vv.x < cm0) { cm0 = vv.x; am0 = q; }
            if (vv.y < cm1) { cm1 = vv.y; am1 = q; }
            if (vv.z < cm2) { cm2 = vv.z; am2 = q; }
            if (vv.w < cm3) { cm3 = vv.w; am3 = q; }
        }
    }
    #pragma unroll
    for (int c = 0; c < 4; ++c) {
        u_s[1 + L + 32 * c] = 0.f;
        rowclaim[L + 32 * c] = -1;
    }
    if (L == 0) u_s[0] = 0.f;
    __syncwarp();

    // ---- Greedy claim: column j grabs its argmin row if still free. ----
    float v[4] = {cm0, cm1, cm2, cm3};      // v[j] = column min (feasible duals)
    unsigned pcol_pack = 0;                  // 4x8-bit: p[4L+c] (row id 1..128, 0=free)
    {
        int am[4] = {am0, am1, am2, am3};
        #pragma unroll
        for (int c = 0; c < 4; ++c) {
            if (atomicCAS(&rowclaim[am[c]], -1, 4 * L + c) == -1)
                pcol_pack |= (unsigned)(am[c] + 1) << (8 * c);
        }
    }
    __syncwarp();

    // ---- Dijkstra phases for remaining free rows. ----
    for (int i = 1; i <= K_; ++i) {
        if (rowclaim[i - 1] >= 0) continue;         // uniform branch

        float minv[4] = {3.0e38f, 3.0e38f, 3.0e38f, 3.0e38f};
        unsigned way_pack = 0;                       // 4x8-bit predecessor col ids
        unsigned used = 0;                           // bit c
        float urow[4];                               // u[p[col]] snapshot (phase start)
        #pragma unroll
        for (int c = 0; c < 4; ++c)
            urow[c] = u_s[(pcol_pack >> (8 * c)) & 0xFFu];
        float ui_new = 0.f;                          // u[i] accumulation

        int j0 = 0, i0 = i;
        float ui0 = 0.f;                             // u[i] == 0 at phase start
        int jfin;
        while (true) {
            if (j0) {
                int idx = j0 - 1;
                if ((idx >> 2) == L) used |= 1u << (idx & 3);
            }
            float4 cr4 = *reinterpret_cast<const float4*>(
                cost_s + (size_t)(i0 - 1) * K_ + 4 * L);
            float cr[4] = {cr4.x, cr4.y, cr4.z, cr4.w};

            unsigned key = 0xFFFFFFFFu;
            int bj = 0, bp = 0; float bu = 0.f;
            #pragma unroll
            for (int c = 0; c < 4; ++c) {
                bool fr = !((used >> c) & 1u);
                float cur = cr[c] - ui0 - v[c];
                if (fr) {
                    if (cur < minv[c]) {
                        minv[c] = cur;
                        way_pack = (way_pack & ~(0xFFu << (8 * c)))
                                 | ((unsigned)j0 << (8 * c));
                    }
                    unsigned kc = fenc(minv[c]);
                    if (kc < key) {
                        key = kc;
                        bj = 4 * L + c + 1;
                        bp = (pcol_pack >> (8 * c)) & 0xFFu;
                        bu = urow[c];
                    }
                }
            }
            unsigned m   = __reduce_min_sync(FULL, key);
            unsigned bal = __ballot_sync(FULL, key == m);
            int srcl = __ffs(bal) - 1;
            int   j1  = __shfl_sync(FULL, bj, srcl);
            int   pj1 = __shfl_sync(FULL, bp, srcl);
            float bu1 = __shfl_sync(FULL, bu, srcl);
            float delta = fdec(m);
            #pragma unroll
            for (int c = 0; c < 4; ++c) {
                if ((used >> c) & 1u) { urow[c] += delta; v[c] -= delta; }
                else                  { minv[c] -= delta; }
            }
            ui_new += delta;
            if (pj1 == 0) { jfin = j1; break; }
            j0 = j1; i0 = pj1; ui0 = bu1;
        }

        // Persist duals for rows touched this phase (distinct rows per column).
        #pragma unroll
        for (int c = 0; c < 4; ++c)
            if ((used >> c) & 1u)
                u_s[(pcol_pack >> (8 * c)) & 0xFFu] = urow[c];
        if (L == 0) u_s[i] = ui_new;

        // Augment along alternating path via register shuffles.
        int jj = jfin;
        while (jj) {
            int idx = jj - 1;
            unsigned wp = __shfl_sync(FULL, way_pack, idx >> 2);
            int jprev = (wp >> (8 * (idx & 3))) & 0xFFu;
            int pv;
            if (jprev == 0) pv = i;
            else {
                int idx2 = jprev - 1;
                unsigned pp = __shfl_sync(FULL, pcol_pack, idx2 >> 2);
                pv = (pp >> (8 * (idx2 & 3))) & 0xFFu;
            }
            if ((idx >> 2) == L) {
                int sl = idx & 3;
                pcol_pack = (pcol_pack & ~(0xFFu << (8 * sl)))
                          | ((unsigned)pv << (8 * sl));
            }
            jj = jprev;
        }
        if (L == 0) rowclaim[i - 1] = 0;            // row i now matched
        __syncwarp();
    }

    // col_ind[p[j]-1] = j  (0-based)
    #pragma unroll
    for (int c = 0; c < 4; ++c) {
        int pr = (pcol_pack >> (8 * c)) & 0xFFu;    // row id 1..128
        g_perm[b * K_ + (pr - 1)] = 4 * L + c;
    }
}

// ---------------------------------------------------------------------------
// Kernel 3: exact MSE (fp32 diffs like reference), fused final reduction.
// ---------------------------------------------------------------------------
__global__ void __launch_bounds__(256) loss_kernel(const float* __restrict__ X,
                                                   const float* __restrict__ Y,
                                                   float* __restrict__ out)
{
    int b = blockIdx.x;
    int tid = threadIdx.x, lane = tid & 31, w = tid >> 5;
    const float* x = X + (size_t)b * K_ * D_;
    const float* y = Y + (size_t)b * K_ * D_;

    float s = 0.f;
    for (int i = w; i < K_; i += 8) {
        int c = g_perm[b * K_ + i];
        const float4* xp = reinterpret_cast<const float4*>(x + (size_t)i * D_);
        const float4* yp = reinterpret_cast<const float4*>(y + (size_t)c * D_);
        #pragma unroll
        for (int q = 0; q < 4; ++q) {
            float4 a  = xp[lane + q * 32];
            float4 bb = yp[lane + q * 32];
            float dx = a.x - bb.x, dy = a.y - bb.y;
            float dz = a.z - bb.z, dw = a.w - bb.w;
            s += dx * dx + dy * dy + dz * dz + dw * dw;
        }
    }
    double ds = (double)s;
    #pragma unroll
    for (int off = 16; off; off >>= 1)
        ds += __shfl_down_sync(0xFFFFFFFFu, ds, off);
    __shared__ double wsum[8];
    if (lane == 0) wsum[w] = ds;
    __syncthreads();
    if (tid == 0) {
        double tot = 0.0;
        #pragma unroll
        for (int q = 0; q < 8; ++q) tot += wsum[q];
        atomicAdd(&g_accum, tot);
        __threadfence();
        unsigned old = atomicInc(&g_count, B_ - 1);   // wraps to 0 on last block
        if (old == B_ - 1) {
            // Last block: read+reset accumulator (self-resetting for replays).
            double total = __longlong_as_double(
                atomicExch((unsigned long long*)&g_accum, 0ULL));
            out[0] = (float)(total / ((double)B_ * K_ * D_));
        }
    }
}

// ---------------------------------------------------------------------------
extern "C" void kernel_launch(void* const* d_in, const int* in_sizes, int n_in,
                              void* d_out, int out_size)
{
    (void)in_sizes; (void)n_in; (void)out_size;
    const float* X = (const float*)d_in[0];
    const float* Y = (const float*)d_in[1];
    float* out = (float*)d_out;

    cudaFuncSetAttribute(hungarian_kernel,
                         cudaFuncAttributeMaxDynamicSharedMemorySize,
                         K_ * K_ * (int)sizeof(float));

    cost_kernel<<<B_, 256>>>(X, Y);
    hungarian_kernel<<<B_, 32, K_ * K_ * sizeof(float)>>>();
    loss_kernel<<<B_, 256>>>(X, Y, out);
}

// round 4
// speedup vs baseline: 3.5123x; 1.2035x over previous
#include <cuda_runtime.h>
#include <cstdint>
#include <cstddef>

#define B_ 512
#define K_ 128
#define D_ 512

// Scratch (static device globals — no allocation in kernel_launch).
__device__ float  g_cost[(size_t)B_ * K_ * K_];   // 32 MB
__device__ int    g_perm[B_ * K_];                // row -> matched column
__device__ double g_accum;                         // zero-init; self-resetting
__device__ unsigned int g_count;                   // zero-init; self-resetting

// ---------------------------------------------------------------------------
// Kernel 1: per-batch cost matrix  C = ||x||^2 + ||y||^2 - 2 X Y^T
// One block per batch, 256 threads, 8x8 register tile per thread.
// ---------------------------------------------------------------------------
__global__ void __launch_bounds__(256) cost_kernel(const float* __restrict__ X,
                                                   const float* __restrict__ Y)
{
    int b = blockIdx.x;
    const float* x = X + (size_t)b * K_ * D_;
    const float* y = Y + (size_t)b * K_ * D_;
    float* cb = g_cost + (size_t)b * K_ * K_;

    __shared__ float xs[32][132];   // [k][i], padded
    __shared__ float ys[32][132];   // [k][j], padded
    __shared__ float sn[2][128];    // row norms of x (0) and y (1)

    int tid = threadIdx.x;

    // Row squared norms: threads 0..127 -> x rows, 128..255 -> y rows.
    {
        const float* src = (tid < 128) ? x : y;
        int r = tid & 127;
        const float4* p4 = reinterpret_cast<const float4*>(src + (size_t)r * D_);
        float s = 0.f;
        #pragma unroll 8
        for (int k = 0; k < D_ / 4; ++k) {
            float4 v = p4[k];
            s += v.x * v.x + v.y * v.y + v.z * v.z + v.w * v.w;
        }
        sn[tid >> 7][r] = s;
    }

    float acc[8][8];
    #pragma unroll
    for (int a = 0; a < 8; ++a)
        #pragma unroll
        for (int c = 0; c < 8; ++c) acc[a][c] = 0.f;

    int ti = tid >> 4;      // 0..15 -> rows ti*8..ti*8+7
    int tj = tid & 15;      // 0..15 -> cols tj*8..tj*8+7

    for (int k0 = 0; k0 < D_; k0 += 32) {
        __syncthreads();
        // Load 128x32 tiles of X and Y, transposed into [k][row].
        #pragma unroll
        for (int l = 0; l < 4; ++l) {
            int f = tid + l * 256;          // 0..1023
            int row = f >> 3;               // 0..127
            int c = f & 7;                  // float4 index along k
            float4 vx = *reinterpret_cast<const float4*>(x + (size_t)row * D_ + k0 + c * 4);
            float4 vy = *reinterpret_cast<const float4*>(y + (size_t)row * D_ + k0 + c * 4);
            int kk = c * 4;
            xs[kk + 0][row] = vx.x; xs[kk + 1][row] = vx.y;
            xs[kk + 2][row] = vx.z; xs[kk + 3][row] = vx.w;
            ys[kk + 0][row] = vy.x; ys[kk + 1][row] = vy.y;
            ys[kk + 2][row] = vy.z; ys[kk + 3][row] = vy.w;
        }
        __syncthreads();
        #pragma unroll 4
        for (int k = 0; k < 32; ++k) {
            float4 t0 = *reinterpret_cast<const float4*>(&xs[k][ti * 8]);
            float4 t1 = *reinterpret_cast<const float4*>(&xs[k][ti * 8 + 4]);
            float4 t2 = *reinterpret_cast<const float4*>(&ys[k][tj * 8]);
            float4 t3 = *reinterpret_cast<const float4*>(&ys[k][tj * 8 + 4]);
            float a[8]  = {t0.x, t0.y, t0.z, t0.w, t1.x, t1.y, t1.z, t1.w};
            float bb[8] = {t2.x, t2.y, t2.z, t2.w, t3.x, t3.y, t3.z, t3.w};
            #pragma unroll
            for (int ii = 0; ii < 8; ++ii)
                #pragma unroll
                for (int jj = 0; jj < 8; ++jj)
                    acc[ii][jj] = fmaf(a[ii], bb[jj], acc[ii][jj]);
        }
    }

    // Write out: c[i][j] = sn_x[i] + sn_y[j] - 2*dot
    #pragma unroll
    for (int ii = 0; ii < 8; ++ii) {
        int i = ti * 8 + ii;
        float sxi = sn[0][i];
        int jb = tj * 8;
        float4 o0, o1;
        o0.x = sxi + sn[1][jb + 0] - 2.f * acc[ii][0];
        o0.y = sxi + sn[1][jb + 1] - 2.f * acc[ii][1];
        o0.z = sxi + sn[1][jb + 2] - 2.f * acc[ii][2];
        o0.w = sxi + sn[1][jb + 3] - 2.f * acc[ii][3];
        o1.x = sxi + sn[1][jb + 4] - 2.f * acc[ii][4];
        o1.y = sxi + sn[1][jb + 5] - 2.f * acc[ii][5];
        o1.z = sxi + sn[1][jb + 6] - 2.f * acc[ii][6];
        o1.w = sxi + sn[1][jb + 7] - 2.f * acc[ii][7];
        *reinterpret_cast<float4*>(&cb[(size_t)i * K_ + jb])     = o0;
        *reinterpret_cast<float4*>(&cb[(size_t)i * K_ + jb + 4]) = o1;
    }
}

// ---------------------------------------------------------------------------
// Kernel 2: Jonker-Volgenant LAP, ONE WARP per batch.
// Lane L owns columns 4L..4L+3 (0-based): cost-row access is one LDS.128.
// Init: column reduction (folded into gmem->smem copy) + greedy row claim
// + lapjv augmenting-row-reduction (ARR). Dijkstra phases only for the few
// remaining free rows. All reduced costs stay >= 0 (feasible duals), so
// float bits compare directly as uint in REDUX.
// ---------------------------------------------------------------------------
__global__ void __launch_bounds__(32) hungarian_kernel()
{
    extern __shared__ float cost_s[];       // K_*K_ floats (64 KB)
    __shared__ float u_s[K_ + 1];           // row duals (row ids 1..K_)
    __shared__ int   rowclaim[K_];          // >=0: row matched, -1: free
    __shared__ int   q_s[3 * K_ + 64];      // ARR work queue (row ids, 1-based)

    const unsigned FULL = 0xFFFFFFFFu;
    int b = blockIdx.x;
    int L = threadIdx.x;

    // ---- Stage cost matrix; fold column-reduction into the copy. ----
    float cm0 = 3.0e38f, cm1 = 3.0e38f, cm2 = 3.0e38f, cm3 = 3.0e38f;
    int   am0 = 0, am1 = 0, am2 = 0, am3 = 0;
    {
        const float4* src = reinterpret_cast<const float4*>(g_cost + (size_t)b * K_ * K_);
        float4* dst = reinterpret_cast<float4*>(cost_s);
        #pragma unroll 8
        for (int q = 0; q < K_; ++q) {
            float4 vv = src[L + 32 * q];
            dst[L + 32 * q] = vv;
            if (vv.x < cm0) { cm0 = vv.x; am0 = q; }
            if (vv.y < cm1) { cm1 = vv.y; am1 = q; }
            if (vv.z < cm2) { cm2 = vv.z; am2 = q; }
            if (vv.w < cm3) { cm3 = vv.w; am3 = q; }
        }
    }
    #pragma unroll
    for (int c = 0; c < 4; ++c) {
        u_s[1 + L + 32 * c] = 0.f;
        rowclaim[L + 32 * c] = -1;
    }
    if (L == 0) u_s[0] = 0.f;
    __syncwarp();

    // ---- Greedy claim: column j grabs its argmin row if still free. ----
    float v[4] = {cm0, cm1, cm2, cm3};      // v[j] = column min (feasible duals)
    unsigned pcol_pack = 0;                  // 4x8-bit: p[4L+c] (row id 1..128, 0=free)
    {
        int am[4] = {am0, am1, am2, am3};
        #pragma unroll
        for (int c = 0; c < 4; ++c) {
            if (atomicCAS(&rowclaim[am[c]], -1, 4 * L + c) == -1)
                pcol_pack |= (unsigned)(am[c] + 1) << (8 * c);
        }
    }
    __syncwarp();

    // ---- Augmenting row reduction (lapjv ARR). ----
    {
        if (L == 0) {
            int n = 0;
            for (int r = 0; r < K_; ++r)
                if (rowclaim[r] < 0) q_s[n++] = r + 1;
            rowclaim[0] = rowclaim[0];      // no-op
            q_s[3 * K_ + 63] = n;           // stash length
        }
        __syncwarp();
        int qlen = q_s[3 * K_ + 63];
        int k = 0;
        int iters = 0;
        const int cap = 3 * K_;
        while (k < qlen && iters < cap) {
            ++iters;
            int i = q_s[k]; ++k;            // broadcast LDS
            const float* crow = cost_s + (size_t)(i - 1) * K_;
            float4 c4 = *reinterpret_cast<const float4*>(crow + 4 * L);
            float r0 = c4.x - v[0], r1 = c4.y - v[1];
            float r2 = c4.z - v[2], r3 = c4.w - v[3];
            // lane min / second-min with column ids
            float lm1 = r0, lm2 = 3.0e38f; int lc = 0, lc2 = 1;
            if (r1 < lm1) { lm2 = lm1; lc2 = lc; lm1 = r1; lc = 1; }
            else          { lm2 = r1; lc2 = 1; }
            if (r2 < lm1) { lm2 = lm1; lc2 = lc; lm1 = r2; lc = 2; }
            else if (r2 < lm2) { lm2 = r2; lc2 = 2; }
            if (r3 < lm1) { lm2 = lm1; lc2 = lc; lm1 = r3; lc = 3; }
            else if (r3 < lm2) { lm2 = r3; lc2 = 3; }

            unsigned k1 = __float_as_uint(lm1);
            unsigned m1 = __reduce_min_sync(FULL, k1);
            unsigned bl = __ballot_sync(FULL, k1 == m1);
            int s1 = __ffs(bl) - 1;
            int j1 = __shfl_sync(FULL, 4 * L + lc + 1, s1);
            unsigned k2 = (L == s1) ? __float_as_uint(lm2) : k1;
            unsigned m2 = __reduce_min_sync(FULL, k2);
            unsigned bl2 = __ballot_sync(FULL, k2 == m2);
            int s2 = __ffs(bl2) - 1;
            int j2cand = (L == s1) ? (4 * L + lc2 + 1) : (4 * L + lc + 1);
            int j2 = __shfl_sync(FULL, j2cand, s2);
            float u1 = __uint_as_float(m1), u2 = __uint_as_float(m2);

            int own1 = (j1 - 1) >> 2, sl1 = (j1 - 1) & 3;
            unsigned pp1 = __shfl_sync(FULL, pcol_pack, own1);
            int i0 = (pp1 >> (8 * sl1)) & 0xFF;
            bool strict = (m1 < m2);
            int jt;
            if (strict) {
                if (L == own1) v[sl1] -= (u2 - u1);
                jt = j1;
            } else if (i0 != 0) {
                jt = j2;
            } else {
                jt = j1;
            }
            int ownt = (jt - 1) >> 2, slt = (jt - 1) & 3;
            unsigned ppt = __shfl_sync(FULL, pcol_pack, ownt);
            int idisp = (ppt >> (8 * slt)) & 0xFF;   // displaced row (0 if free)
            if (L == ownt)
                pcol_pack = (pcol_pack & ~(0xFFu << (8 * slt)))
                          | ((unsigned)i << (8 * slt));
            if (L == 0) {
                u_s[i] = u2;                 // tight at jt in all branches
                rowclaim[i - 1] = jt - 1;
            }
            if (idisp != 0) {
                if (L == 0) rowclaim[idisp - 1] = -1;
                if (strict) { --k; if (L == 0) q_s[k] = idisp; }
                else        { if (L == 0) q_s[qlen] = idisp; ++qlen; }
            }
            __syncwarp();
        }
    }

    // ---- Dijkstra phases for remaining free rows. ----
    for (int i = 1; i <= K_; ++i) {
        if (rowclaim[i - 1] >= 0) continue;          // uniform branch

        float minv[4] = {3.0e38f, 3.0e38f, 3.0e38f, 3.0e38f};
        unsigned way_pack = 0;                       // 4x8-bit predecessor col ids
        unsigned used = 0;                           // bit c
        float urow[4];                               // u[p[col]] running values
        #pragma unroll
        for (int c = 0; c < 4; ++c)
            urow[c] = u_s[(pcol_pack >> (8 * c)) & 0xFFu];
        float ui_new = u_s[i];                       // free row may carry ARR dual

        int j0 = 0, i0 = i;
        float ui0 = ui_new;
        int jfin;
        while (true) {
            if (j0) {
                int idx = j0 - 1;
                if ((idx >> 2) == L) used |= 1u << (idx & 3);
            }
            float4 cr4 = *reinterpret_cast<const float4*>(
                cost_s + (size_t)(i0 - 1) * K_ + 4 * L);
            float cr[4] = {cr4.x, cr4.y, cr4.z, cr4.w};

            unsigned key = 0xFFFFFFFFu;
            int bjp = 0; float bu = 0.f;
            #pragma unroll
            for (int c = 0; c < 4; ++c) {
                bool fr = !((used >> c) & 1u);
                float cur = cr[c] - ui0 - v[c];
                if (fr) {
                    if (cur < minv[c]) {
                        minv[c] = cur;
                        way_pack = (way_pack & ~(0xFFu << (8 * c)))
                                 | ((unsigned)j0 << (8 * c));
                    }
                    unsigned kc = __float_as_uint(minv[c]);   // >= 0 always
                    if (kc < key) {
                        key = kc;
                        bjp = ((4 * L + c + 1) << 8) | ((pcol_pack >> (8 * c)) & 0xFFu);
                        bu = urow[c];
                    }
                }
            }
            unsigned m   = __reduce_min_sync(FULL, key);
            unsigned bal = __ballot_sync(FULL, key == m);
            int srcl = __ffs(bal) - 1;
            int   jp  = __shfl_sync(FULL, bjp, srcl);
            float bu1 = __shfl_sync(FULL, bu, srcl);
            int j1  = jp >> 8;
            int pj1 = jp & 0xFF;
            float delta = __uint_as_float(m);
            #pragma unroll
            for (int c = 0; c < 4; ++c) {
                if ((used >> c) & 1u) { urow[c] += delta; v[c] -= delta; }
                else                  { minv[c] -= delta; }
            }
            ui_new += delta;
            if (pj1 == 0) { jfin = j1; break; }
            j0 = j1; i0 = pj1; ui0 = bu1;
        }

        // Persist duals for rows touched this phase (distinct rows per column).
        #pragma unroll
        for (int c = 0; c < 4; ++c)
            if ((used >> c) & 1u)
                u_s[(pcol_pack >> (8 * c)) & 0xFFu] = urow[c];
        if (L == 0) u_s[i] = ui_new;

        // Augment along alternating path via register shuffles.
        int jj = jfin;
        while (jj) {
            int idx = jj - 1;
            unsigned wp = __shfl_sync(FULL, way_pack, idx >> 2);
            int jprev = (wp >> (8 * (idx & 3))) & 0xFFu;
            int pv;
            if (jprev == 0) pv = i;
            else {
                int idx2 = jprev - 1;
                unsigned pp = __shfl_sync(FULL, pcol_pack, idx2 >> 2);
                pv = (pp >> (8 * (idx2 & 3))) & 0xFFu;
            }
            if ((idx >> 2) == L) {
                int sl = idx & 3;
                pcol_pack = (pcol_pack & ~(0xFFu << (8 * sl)))
                          | ((unsigned)pv << (8 * sl));
            }
            jj = jprev;
        }
        if (L == 0) rowclaim[i - 1] = 0;            // row i now matched
        __syncwarp();
    }

    // col_ind[p[j]-1] = j  (0-based)
    #pragma unroll
    for (int c = 0; c < 4; ++c) {
        int pr = (pcol_pack >> (8 * c)) & 0xFFu;    // row id 1..128
        g_perm[b * K_ + (pr - 1)] = 4 * L + c;
    }
}

// ---------------------------------------------------------------------------
// Kernel 3: exact MSE (fp32 diffs like reference), fused final reduction.
// ---------------------------------------------------------------------------
__global__ void __launch_bounds__(256) loss_kernel(const float* __restrict__ X,
                                                   const float* __restrict__ Y,
                                                   float* __restrict__ out)
{
    int b = blockIdx.x;
    int tid = threadIdx.x, lane = tid & 31, w = tid >> 5;
    const float* x = X + (size_t)b * K_ * D_;
    const float* y = Y + (size_t)b * K_ * D_;

    float s = 0.f;
    for (int i = w; i < K_; i += 8) {
        int c = g_perm[b * K_ + i];
        const float4* xp = reinterpret_cast<const float4*>(x + (size_t)i * D_);
        const float4* yp = reinterpret_cast<const float4*>(y + (size_t)c * D_);
        #pragma unroll
        for (int q = 0; q < 4; ++q) {
            float4 a  = xp[lane + q * 32];
            float4 bb = yp[lane + q * 32];
            float dx = a.x - bb.x, dy = a.y - bb.y;
            float dz = a.z - bb.z, dw = a.w - bb.w;
            s += dx * dx + dy * dy + dz * dz + dw * dw;
        }
    }
    double ds = (double)s;
    #pragma unroll
    for (int off = 16; off; off >>= 1)
        ds += __shfl_down_sync(0xFFFFFFFFu, ds, off);
    __shared__ double wsum[8];
    if (lane == 0) wsum[w] = ds;
    __syncthreads();
    if (tid == 0) {
        double tot = 0.0;
        #pragma unroll
        for (int q = 0; q < 8; ++q) tot += wsum[q];
        atomicAdd(&g_accum, tot);
        __threadfence();
        unsigned old = atomicInc(&g_count, B_ - 1);   // wraps to 0 on last block
        if (old == B_ - 1) {
            double total = __longlong_as_double(
                atomicExch((unsigned long long*)&g_accum, 0ULL));
            out[0] = (float)(total / ((double)B_ * K_ * D_));
        }
    }
}

// ---------------------------------------------------------------------------
extern "C" void kernel_launch(void* const* d_in, const int* in_sizes, int n_in,
                              void* d_out, int out_size)
{
    (void)in_sizes; (void)n_in; (void)out_size;
    const float* X = (const float*)d_in[0];
    const float* Y = (const float*)d_in[1];
    float* out = (float*)d_out;

    cudaFuncSetAttribute(hungarian_kernel,
                         cudaFuncAttributeMaxDynamicSharedMemorySize,
                         K_ * K_ * (int)sizeof(float));

    cost_kernel<<<B_, 256>>>(X, Y);
    hungarian_kernel<<<B_, 32, K_ * K_ * sizeof(float)>>>();
    loss_kernel<<<B_, 256>>>(X, Y, out);
}

// round 5
// speedup vs baseline: 4.4099x; 1.2556x over previous
#include <cuda_runtime.h>
#include <cstdint>
#include <cstddef>

#define B_ 512
#define K_ 128
#define D_ 512

// Scratch (static device globals — no allocation in kernel_launch).
__device__ float  g_cost[(size_t)B_ * K_ * K_];   // 32 MB
__device__ int    g_perm[B_ * K_];                // row -> matched column
__device__ double g_accum;                         // zero-init; self-resetting
__device__ unsigned int g_count;                   // zero-init; self-resetting

// ---------------------------------------------------------------------------
// Kernel 1: per-batch cost matrix  C = ||x||^2 + ||y||^2 - 2 X Y^T
// One block per batch, 8 warps. tf32 mma.sync.m16n8k8 (raw fp32 bits as tf32,
// RZ truncation). Warp tile 32x64: 2 m-tiles (16) x 8 n-tiles (8).
// Smem tiles 128x32 fp32 padded to stride 36 -> conflict-free fragments.
// Norms computed fp32-exact; only the cross term goes through tf32.
// ---------------------------------------------------------------------------
__device__ __forceinline__ void mma_tf32(float* c, unsigned a0, unsigned a1,
                                         unsigned a2, unsigned a3,
                                         unsigned b0, unsigned b1)
{
    asm volatile(
        "mma.sync.aligned.m16n8k8.row.col.f32.tf32.tf32.f32 "
        "{%0,%1,%2,%3}, {%4,%5,%6,%7}, {%8,%9}, {%0,%1,%2,%3};"
        : "+f"(c[0]), "+f"(c[1]), "+f"(c[2]), "+f"(c[3])
        : "r"(a0), "r"(a1), "r"(a2), "r"(a3), "r"(b0), "r"(b1));
}

#define XS_STRIDE 36

__global__ void __launch_bounds__(256) cost_kernel(const float* __restrict__ X,
                                                   const float* __restrict__ Y)
{
    int b = blockIdx.x;
    const float* x = X + (size_t)b * K_ * D_;
    const float* y = Y + (size_t)b * K_ * D_;
    float* cb = g_cost + (size_t)b * K_ * K_;

    __shared__ float xs[K_ * XS_STRIDE];
    __shared__ float ys[K_ * XS_STRIDE];
    __shared__ float sn[2][K_];

    int tid = threadIdx.x;
    int w = tid >> 5, lane = tid & 31;
    int g = lane >> 2, tig = lane & 3;
    int m0 = (w & 3) * 32;          // 4 m-warps
    int n0 = (w >> 2) * 64;         // 2 n-warps

    // Row squared norms (exact fp32).
    {
        const float* src = (tid < 128) ? x : y;
        int r = tid & 127;
        const float4* p4 = reinterpret_cast<const float4*>(src + (size_t)r * D_);
        float s = 0.f;
        #pragma unroll 8
        for (int k = 0; k < D_ / 4; ++k) {
            float4 vv = p4[k];
            s += vv.x * vv.x + vv.y * vv.y + vv.z * vv.z + vv.w * vv.w;
        }
        sn[tid >> 7][r] = s;
    }

    float acc[2][8][4];
    #pragma unroll
    for (int mt = 0; mt < 2; ++mt)
        #pragma unroll
        for (int nt = 0; nt < 8; ++nt)
            #pragma unroll
            for (int q = 0; q < 4; ++q) acc[mt][nt][q] = 0.f;

    for (int k0 = 0; k0 < D_; k0 += 32) {
        __syncthreads();
        // Fill 128x32 tiles (4 float4 per thread per matrix), padded stride.
        #pragma unroll
        for (int l = 0; l < 4; ++l) {
            int f = tid + l * 256;          // 0..1023
            int row = f >> 3;               // 0..127
            int c4 = f & 7;                 // float4 within the 32-wide row
            float4 vx = *reinterpret_cast<const float4*>(x + (size_t)row * D_ + k0 + c4 * 4);
            float4 vy = *reinterpret_cast<const float4*>(y + (size_t)row * D_ + k0 + c4 * 4);
            float* xd = xs + row * XS_STRIDE + c4 * 4;
            float* yd = ys + row * XS_STRIDE + c4 * 4;
            xd[0] = vx.x; xd[1] = vx.y; xd[2] = vx.z; xd[3] = vx.w;
            yd[0] = vy.x; yd[1] = vy.y; yd[2] = vy.z; yd[3] = vy.w;
        }
        __syncthreads();

        #pragma unroll
        for (int ks = 0; ks < 32; ks += 8) {
            unsigned a[2][4];
            #pragma unroll
            for (int mt = 0; mt < 2; ++mt) {
                int r = m0 + mt * 16 + g;
                a[mt][0] = __float_as_uint(xs[r * XS_STRIDE + ks + tig]);
                a[mt][1] = __float_as_uint(xs[(r + 8) * XS_STRIDE + ks + tig]);
                a[mt][2] = __float_as_uint(xs[r * XS_STRIDE + ks + tig + 4]);
                a[mt][3] = __float_as_uint(xs[(r + 8) * XS_STRIDE + ks + tig + 4]);
            }
            #pragma unroll
            for (int nt = 0; nt < 8; ++nt) {
                int cn = n0 + nt * 8 + g;
                unsigned b0 = __float_as_uint(ys[cn * XS_STRIDE + ks + tig]);
                unsigned b1 = __float_as_uint(ys[cn * XS_STRIDE + ks + tig + 4]);
                mma_tf32(acc[0][nt], a[0][0], a[0][1], a[0][2], a[0][3], b0, b1);
                mma_tf32(acc[1][nt], a[1][0], a[1][1], a[1][2], a[1][3], b0, b1);
            }
        }
    }

    // Epilogue: C[i][j] = sx[i] + sy[j] - 2*dot
    #pragma unroll
    for (int mt = 0; mt < 2; ++mt) {
        int i0r = m0 + mt * 16 + g;
        float sx0 = sn[0][i0r];
        float sx1 = sn[0][i0r + 8];
        #pragma unroll
        for (int nt = 0; nt < 8; ++nt) {
            int j = n0 + nt * 8 + 2 * tig;
            float sy0 = sn[1][j], sy1 = sn[1][j + 1];
            float2 o0, o1;
            o0.x = sx0 + sy0 - 2.f * acc[mt][nt][0];
            o0.y = sx0 + sy1 - 2.f * acc[mt][nt][1];
            o1.x = sx1 + sy0 - 2.f * acc[mt][nt][2];
            o1.y = sx1 + sy1 - 2.f * acc[mt][nt][3];
            *reinterpret_cast<float2*>(&cb[(size_t)i0r * K_ + j])       = o0;
            *reinterpret_cast<float2*>(&cb[(size_t)(i0r + 8) * K_ + j]) = o1;
        }
    }
}

// ---------------------------------------------------------------------------
// Kernel 2: Jonker-Volgenant LAP, ONE WARP per batch.
// Lane L owns columns 4L..4L+3 (0-based): cost-row access is one LDS.128.
// Argmin is fused into REDUX: key = (minv_bits & ~0xFF) | col. delta uses the
// truncated min (<= every true minv), so reduced costs stay >= 0; edges are
// eps-tight (eps <= 255 ulp) -> permutation eps-optimal (negligible in loss).
// Init: column reduction (folded into copy) + greedy claim + lapjv ARR.
// ---------------------------------------------------------------------------
__global__ void __launch_bounds__(32) hungarian_kernel()
{
    extern __shared__ float cost_s[];       // K_*K_ floats (64 KB)
    __shared__ float u_s[K_ + 1];           // row duals (row ids 1..K_)
    __shared__ int   rowclaim[K_];          // >=0: row matched, -1: free
    __shared__ int   q_s[4 * K_ + 8];       // ARR work queue (row ids, 1-based)

    const unsigned FULL = 0xFFFFFFFFu;
    int b = blockIdx.x;
    int L = threadIdx.x;

    // ---- Stage cost matrix; fold column-reduction into the copy. ----
    float cm0 = 3.0e38f, cm1 = 3.0e38f, cm2 = 3.0e38f, cm3 = 3.0e38f;
    int   am0 = 0, am1 = 0, am2 = 0, am3 = 0;
    {
        const float4* src = reinterpret_cast<const float4*>(g_cost + (size_t)b * K_ * K_);
        float4* dst = reinterpret_cast<float4*>(cost_s);
        #pragma unroll 8
        for (int q = 0; q < K_; ++q) {
            float4 vv = src[L + 32 * q];
            dst[L + 32 * q] = vv;
            if (vv.x < cm0) { cm0 = vv.x; am0 = q; }
            if (vv.y < cm1) { cm1 = vv.y; am1 = q; }
            if (vv.z < cm2) { cm2 = vv.z; am2 = q; }
            if (vv.w < cm3) { cm3 = vv.w; am3 = q; }
        }
    }
    #pragma unroll
    for (int c = 0; c < 4; ++c) {
        u_s[1 + L + 32 * c] = 0.f;
        rowclaim[L + 32 * c] = -1;
    }
    if (L == 0) u_s[0] = 0.f;
    __syncwarp();

    // ---- Greedy claim: column j grabs its argmin row if still free. ----
    float v[4] = {cm0, cm1, cm2, cm3};      // v[j] = column min (feasible duals)
    unsigned pcol_pack = 0;                  // 4x8-bit: p[4L+c] (row id 1..128, 0=free)
    {
        int am[4] = {am0, am1, am2, am3};
        #pragma unroll
        for (int c = 0; c < 4; ++c) {
            if (atomicCAS(&rowclaim[am[c]], -1, 4 * L + c) == -1)
                pcol_pack |= (unsigned)(am[c] + 1) << (8 * c);
        }
    }
    __syncwarp();

    // ---- Augmenting row reduction (lapjv ARR). ----
    {
        if (L == 0) {
            int n = 0;
            for (int r = 0; r < K_; ++r)
                if (rowclaim[r] < 0) q_s[n++] = r + 1;
            q_s[4 * K_ + 4] = n;             // stash length
        }
        __syncwarp();
        int qlen = q_s[4 * K_ + 4];
        int k = 0;
        int iters = 0;
        const int cap = 3 * K_;
        while (k < qlen && iters < cap) {
            ++iters;
            int i = q_s[k]; ++k;            // broadcast LDS
            const float* crow = cost_s + (size_t)(i - 1) * K_;
            float4 c4 = *reinterpret_cast<const float4*>(crow + 4 * L);
            float r0 = fmaxf(c4.x - v[0], 0.f), r1 = fmaxf(c4.y - v[1], 0.f);
            float r2 = fmaxf(c4.z - v[2], 0.f), r3 = fmaxf(c4.w - v[3], 0.f);
            // lane min / second-min with column slots
            float lm1 = r0, lm2 = 3.0e38f; int lc = 0, lc2 = 1;
            if (r1 < lm1) { lm2 = lm1; lc2 = lc; lm1 = r1; lc = 1; }
            else          { lm2 = r1; lc2 = 1; }
            if (r2 < lm1) { lm2 = lm1; lc2 = lc; lm1 = r2; lc = 2; }
            else if (r2 < lm2) { lm2 = r2; lc2 = 2; }
            if (r3 < lm1) { lm2 = lm1; lc2 = lc; lm1 = r3; lc = 3; }
            else if (r3 < lm2) { lm2 = r3; lc2 = 3; }

            unsigned k1 = (__float_as_uint(lm1) & 0xFFFFFF00u) | (unsigned)(4 * L + lc);
            unsigned m1 = __reduce_min_sync(FULL, k1);
            int j1_0 = m1 & 0xFF;
            int wl1 = j1_0 >> 2;
            unsigned k2 = (L == wl1)
                ? ((__float_as_uint(lm2) & 0xFFFFFF00u) | (unsigned)(4 * L + lc2))
                : k1;
            unsigned m2 = __reduce_min_sync(FULL, k2);
            int j2_0 = m2 & 0xFF;
            float u1 = __uint_as_float(m1 & 0xFFFFFF00u);
            float u2 = __uint_as_float(m2 & 0xFFFFFF00u);
            bool strict = (m1 >> 8) < (m2 >> 8);

            unsigned pp1 = __shfl_sync(FULL, pcol_pack, wl1);
            int i0 = (pp1 >> (8 * (j1_0 & 3))) & 0xFF;
            int jt_0;
            if (strict) {
                #pragma unroll
                for (int c = 0; c < 4; ++c)
                    if (L == wl1 && c == (j1_0 & 3)) v[c] -= (u2 - u1);
                jt_0 = j1_0;
            } else if (i0 != 0) {
                jt_0 = j2_0;
            } else {
                jt_0 = j1_0;
            }
            int ownt = jt_0 >> 2, slt = jt_0 & 3;
            unsigned ppt = __shfl_sync(FULL, pcol_pack, ownt);
            int idisp = (ppt >> (8 * slt)) & 0xFF;   // displaced row (0 if free)
            if (L == ownt)
                pcol_pack = (pcol_pack & ~(0xFFu << (8 * slt)))
                          | ((unsigned)i << (8 * slt));
            if (L == 0) {
                u_s[i] = u2;
                rowclaim[i - 1] = jt_0;
            }
            if (idisp != 0) {
                if (L == 0) rowclaim[idisp - 1] = -1;
                if (strict) { --k; if (L == 0) q_s[k] = idisp; }
                else        { if (L == 0) q_s[qlen] = idisp; ++qlen; }
            }
            __syncwarp();
        }
    }

    // ---- Dijkstra phases for remaining free rows. ----
    for (int i = 1; i <= K_; ++i) {
        if (rowclaim[i - 1] >= 0) continue;          // uniform branch

        float minv[4] = {3.0e38f, 3.0e38f, 3.0e38f, 3.0e38f};
        unsigned way_pack = 0;                       // 4x8-bit predecessor col ids
        unsigned used = 0;                           // bit c
        float urow[4];                               // u[p[col]] running values
        #pragma unroll
        for (int c = 0; c < 4; ++c)
            urow[c] = u_s[(pcol_pack >> (8 * c)) & 0xFFu];
        float ui_new = u_s[i];                       // free row may carry ARR dual

        int j0 = 0, i0 = i;
        float ui0 = ui_new;
        int jfin;
        while (true) {
            float4 cr4 = *reinterpret_cast<const float4*>(
                cost_s + (size_t)(i0 - 1) * K_ + 4 * L);
            float cr[4] = {cr4.x, cr4.y, cr4.z, cr4.w};

            unsigned key = 0xFFFFFFFFu;
            float bu = 0.f;
            #pragma unroll
            for (int c = 0; c < 4; ++c) {
                bool fr = !((used >> c) & 1u);
                float cur = fmaxf(cr[c] - ui0 - v[c], 0.f);
                if (fr) {
                    if (cur < minv[c]) {
                        minv[c] = cur;
                        way_pack = (way_pack & ~(0xFFu << (8 * c)))
                                 | ((unsigned)j0 << (8 * c));
                    }
                    unsigned kc = (__float_as_uint(minv[c]) & 0xFFFFFF00u)
                                | (unsigned)(4 * L + c);
                    if (kc < key) { key = kc; bu = urow[c]; }
                }
            }
            unsigned m = __reduce_min_sync(FULL, key);
            int j1_0 = m & 0xFF;
            int wl = j1_0 >> 2, slot = j1_0 & 3;
            float ui1   = __shfl_sync(FULL, bu, wl);
            unsigned pp = __shfl_sync(FULL, pcol_pack, wl);
            int pj1 = (pp >> (8 * slot)) & 0xFF;
            float delta = __uint_as_float(m & 0xFFFFFF00u);
            #pragma unroll
            for (int c = 0; c < 4; ++c) {
                if ((used >> c) & 1u) { urow[c] += delta; v[c] -= delta; }
                else                  { minv[c] -= delta; }
            }
            ui_new += delta;
            if (L == wl) used |= 1u << slot;
            if (pj1 == 0) { jfin = j1_0 + 1; break; }
            j0 = j1_0 + 1; i0 = pj1; ui0 = ui1;
        }

        // Persist duals for rows touched this phase (distinct rows per column).
        #pragma unroll
        for (int c = 0; c < 4; ++c)
            if ((used >> c) & 1u)
                u_s[(pcol_pack >> (8 * c)) & 0xFFu] = urow[c];
        if (L == 0) u_s[i] = ui_new;

        // Augment along alternating path via register shuffles.
        int jj = jfin;
        while (jj) {
            int idx = jj - 1;
            unsigned wp = __shfl_sync(FULL, way_pack, idx >> 2);
            int jprev = (wp >> (8 * (idx & 3))) & 0xFFu;
            int pv;
            if (jprev == 0) pv = i;
            else {
                int idx2 = jprev - 1;
                unsigned pp2 = __shfl_sync(FULL, pcol_pack, idx2 >> 2);
                pv = (pp2 >> (8 * (idx2 & 3))) & 0xFFu;
            }
            if ((idx >> 2) == L) {
                int sl = idx & 3;
                pcol_pack = (pcol_pack & ~(0xFFu << (8 * sl)))
                          | ((unsigned)pv << (8 * sl));
            }
            jj = jprev;
        }
        if (L == 0) rowclaim[i - 1] = 0;            // row i now matched
        __syncwarp();
    }

    // col_ind[p[j]-1] = j  (0-based)
    #pragma unroll
    for (int c = 0; c < 4; ++c) {
        int pr = (pcol_pack >> (8 * c)) & 0xFFu;    // row id 1..128
        g_perm[b * K_ + (pr - 1)] = 4 * L + c;
    }
}

// ---------------------------------------------------------------------------
// Kernel 3: exact MSE (fp32 diffs like reference), fused final reduction.
// ---------------------------------------------------------------------------
__global__ void __launch_bounds__(256) loss_kernel(const float* __restrict__ X,
                                                   const float* __restrict__ Y,
                                                   float* __restrict__ out)
{
    int b = blockIdx.x;
    int tid = threadIdx.x, lane = tid & 31, w = tid >> 5;
    const float* x = X + (size_t)b * K_ * D_;
    const float* y = Y + (size_t)b * K_ * D_;

    float s = 0.f;
    for (int i = w; i < K_; i += 8) {
        int c = g_perm[b * K_ + i];
        const float4* xp = reinterpret_cast<const float4*>(x + (size_t)i * D_);
        const float4* yp = reinterpret_cast<const float4*>(y + (size_t)c * D_);
        #pragma unroll
        for (int q = 0; q < 4; ++q) {
            float4 a  = xp[lane + q * 32];
            float4 bb = yp[lane + q * 32];
            float dx = a.x - bb.x, dy = a.y - bb.y;
            float dz = a.z - bb.z, dw = a.w - bb.w;
            s += dx * dx + dy * dy + dz * dz + dw * dw;
        }
    }
    double ds = (double)s;
    #pragma unroll
    for (int off = 16; off; off >>= 1)
        ds += __shfl_down_sync(0xFFFFFFFFu, ds, off);
    __shared__ double wsum[8];
    if (lane == 0) wsum[w] = ds;
    __syncthreads();
    if (tid == 0) {
        double tot = 0.0;
        #pragma unroll
        for (int q = 0; q < 8; ++q) tot += wsum[q];
        atomicAdd(&g_accum, tot);
        __threadfence();
        unsigned old = atomicInc(&g_count, B_ - 1);   // wraps to 0 on last block
        if (old == B_ - 1) {
            double total = __longlong_as_double(
                atomicExch((unsigned long long*)&g_accum, 0ULL));
            out[0] = (float)(total / ((double)B_ * K_ * D_));
        }
    }
}

// ---------------------------------------------------------------------------
extern "C" void kernel_launch(void* const* d_in, const int* in_sizes, int n_in,
                              void* d_out, int out_size)
{
    (void)in_sizes; (void)n_in; (void)out_size;
    const float* X = (const float*)d_in[0];
    const float* Y = (const float*)d_in[1];
    float* out = (float*)d_out;

    cudaFuncSetAttribute(hungarian_kernel,
                         cudaFuncAttributeMaxDynamicSharedMemorySize,
                         K_ * K_ * (int)sizeof(float));

    cost_kernel<<<B_, 256>>>(X, Y);
    hungarian_kernel<<<B_, 32, K_ * K_ * sizeof(float)>>>();
    loss_kernel<<<B_, 256>>>(X, Y, out);
}